// round 4
// baseline (speedup 1.0000x reference)
#include <cuda_runtime.h>
#include <cstdint>
#include <cstddef>

#define B_ 8
#define N_ 4096
#define M_ 4096
#define C_ 256

#define SPLITS 8
#define KM_PER_SPLIT 16      // 16 * 32 = 512 m-rows per split

#define STA 136              // stride (words) for kv's raw-v [32][128] tile

// Packed-layout scratch (static device arrays; no allocations allowed).
// qn: [b][n_tile 32][km 8][kk 4][row_tile 8][lane 32][w 4]  (A-fragment order)
// kn: [b][c_tile 2][m_chunk 128][kk 4][c16_tile 8][lane 32][w 4]
// kv: [b][d_tile 2][km 8][kk 4][d8_tile 16][lane 32][w 2]   (B-fragment order)
__device__ uint32_t g_qn[B_ * N_ * C_];
__device__ uint32_t g_kn[B_ * M_ * C_];
__device__ float    g_kvp[SPLITS * B_ * C_ * C_];
__device__ uint32_t g_kv[B_ * C_ * C_];

__device__ __forceinline__ uint32_t f2tf(float x) {
    uint32_t r;
    asm("cvt.rna.tf32.f32 %0, %1;" : "=r"(r) : "f"(x));
    return r;
}

__device__ __forceinline__ void mma8(float c[4], const uint32_t a[4], const uint32_t b[2]) {
    asm volatile(
        "mma.sync.aligned.m16n8k8.row.col.f32.tf32.tf32.f32 "
        "{%0,%1,%2,%3}, {%4,%5,%6,%7}, {%8,%9}, {%0,%1,%2,%3};\n"
        : "+f"(c[0]), "+f"(c[1]), "+f"(c[2]), "+f"(c[3])
        : "r"(a[0]), "r"(a[1]), "r"(a[2]), "r"(a[3]),
          "r"(b[0]), "r"(b[1]));
}

__device__ __forceinline__ void cp16(void* smem, const void* gmem) {
    uint32_t s = (uint32_t)__cvta_generic_to_shared(smem);
    asm volatile("cp.async.cg.shared.global [%0], [%1], 16;\n" :: "r"(s), "l"(gmem));
}
__device__ __forceinline__ void cp_commit() { asm volatile("cp.async.commit_group;\n" ::: "memory"); }
template <int NN>
__device__ __forceinline__ void cp_wait() { asm volatile("cp.async.wait_group %0;\n" :: "n"(NN) : "memory"); }

// ---------------------------------------------------------------------------
// Kernel 1 (prep): warp per row. Normalize, tf32-convert, and scatter into
// MMA-fragment-packed layouts.
//   q rows -> qn = tf32(q / (N*max(||q||,eps)))   [A-frag layout for ctx]
//   k rows -> kn = tf32(k / max(||k||,eps))       [A-frag layout for kv]
// ---------------------------------------------------------------------------
__global__ __launch_bounds__(256) void prep_kernel(const float* __restrict__ q,
                                                   const float* __restrict__ k) {
    const int gw = (blockIdx.x * blockDim.x + threadIdx.x) >> 5;   // row id
    const int lane = threadIdx.x & 31;
    const bool is_q = (gw < B_ * N_);
    const int r = is_q ? gw : gw - B_ * N_;
    const float* src = (is_q ? q : k) + (size_t)r * C_;

    float4 a = *(const float4*)(src + lane * 4);
    float4 bb = *(const float4*)(src + 128 + lane * 4);
    float ss = a.x * a.x + a.y * a.y + a.z * a.z + a.w * a.w
             + bb.x * bb.x + bb.y * bb.y + bb.z * bb.z + bb.w * bb.w;
#pragma unroll
    for (int o = 16; o > 0; o >>= 1) ss += __shfl_xor_sync(0xffffffffu, ss, o);
    float rn = (ss > 1e-24f) ? rsqrtf(ss) : 1e12f;
    if (is_q) rn *= (1.0f / (float)N_);

    float vals[8] = {a.x, a.y, a.z, a.w, bb.x, bb.y, bb.z, bb.w};
    const int b = r >> 12;          // row / 4096
    const int rr = r & 4095;

    if (is_q) {
        const int n_tile = rr >> 7;
        const int rl = rr & 127;
        const int rt = rl >> 4;
        const int g = rl & 7;
        const int h = (rl >> 3) & 1;
        uint32_t* base = g_qn + (size_t)(b * 32 + n_tile) * 32768;
#pragma unroll
        for (int i = 0; i < 8; i++) {
            const int c = (i < 4) ? (lane * 4 + i) : (128 + lane * 4 + (i - 4));
            const int km = c >> 5, kk = (c >> 3) & 3, tig = c & 3, j = (c >> 2) & 1;
            const int off = (((km * 4 + kk) * 8 + rt) * 32 + (g * 4 + tig)) * 4 + h + 2 * j;
            base[off] = f2tf(vals[i] * rn);
        }
    } else {
        const int m = rr;
        const int m_chunk = m >> 5, kk = (m >> 3) & 3, tig = m & 3, j = (m >> 2) & 1;
        const int wbase = (kk * 8) * 128;   // partial: kk stride applied below
#pragma unroll
        for (int i = 0; i < 8; i++) {
            const int c = (i < 4) ? (lane * 4 + i) : (128 + lane * 4 + (i - 4));
            const int ct = c >> 7;
            const int cl = c & 127;
            const int c16t = cl >> 4;
            const int g = cl & 7;
            const int h = (cl >> 3) & 1;
            size_t off = ((size_t)((b * 2 + ct) * 128 + m_chunk) * 4096)
                       + (size_t)wbase + (size_t)c16t * 128
                       + (g * 4 + tig) * 4 + h + 2 * j;
            g_kn[off] = f2tf(vals[i] * rn);
        }
    }
}

// ---------------------------------------------------------------------------
// Kernel 2: split-K partials of kv[b][c][d] = sum_m kn[b][m][c] * v[b][m][d]
// CTA tile 128(c) x 128(d), BK=32, 2-stage cp.async pipeline, 2 CTAs/SM.
// A (kn) fragment-packed: 4x LDS.128 per kk. B (v) raw fp32: 8 LDS + 8 cvt.
// ---------------------------------------------------------------------------
__global__ __launch_bounds__(256, 2) void kv_kernel(const float* __restrict__ v) {
    extern __shared__ uint32_t sm[];
    uint32_t* As = sm;                        // [2][4096]  packed A
    float*    Bs = (float*)(sm + 2 * 4096);   // [2][32*STA] raw fp32

    const int bz = blockIdx.z;       // b*8 + split
    const int b  = bz >> 3;
    const int sp = bz & 7;
    const int c_tile = blockIdx.y;   // 0..1
    const int c0 = c_tile * 128;
    const int d0 = blockIdx.x * 128;
    const int m_base = sp * (KM_PER_SPLIT * 32);

    const int t = threadIdx.x, lane = t & 31, wid = t >> 5;
    const int g = lane >> 2, tig = lane & 3;
    const int wc = (wid >> 2) * 64;
    const int wd = (wid & 3) * 32;

    const int lr = t >> 3;           // v tile row 0..31
    const int lq = (t & 7) * 4;      // word col base, iterate +32

    const uint32_t* knb = g_kn + (size_t)((b * 2 + c_tile) * 128) * 4096;
    const float*    vb  = v + (size_t)b * M_ * C_ + d0;

    // prologue: stage 0
    {
        const uint32_t* srcA = knb + (size_t)(sp * KM_PER_SPLIT) * 4096;
#pragma unroll
        for (int i = 0; i < 4; i++)
            cp16(&As[t * 4 + i * 1024], srcA + t * 4 + i * 1024);
#pragma unroll
        for (int i = 0; i < 4; i++)
            cp16(&Bs[lr * STA + lq + i * 32], vb + (size_t)(m_base + lr) * C_ + lq + i * 32);
        cp_commit();
    }

    float acc[4][4][4] = {};

#pragma unroll 1
    for (int km = 0; km < KM_PER_SPLIT; km++) {
        const int cur = km & 1;
        if (km + 1 < KM_PER_SPLIT) {
            const int nxt = cur ^ 1;
            const uint32_t* srcA = knb + (size_t)(sp * KM_PER_SPLIT + km + 1) * 4096;
            uint32_t* An = &As[nxt * 4096];
            float*    Bn = &Bs[nxt * 32 * STA];
            const int m0 = m_base + (km + 1) * 32;
#pragma unroll
            for (int i = 0; i < 4; i++)
                cp16(&An[t * 4 + i * 1024], srcA + t * 4 + i * 1024);
#pragma unroll
            for (int i = 0; i < 4; i++)
                cp16(&Bn[lr * STA + lq + i * 32], vb + (size_t)(m0 + lr) * C_ + lq + i * 32);
            cp_commit();
            cp_wait<1>();
        } else {
            cp_wait<0>();
        }
        __syncthreads();

        const uint32_t* Ac = &As[cur * 4096];
        const float*    Bc = &Bs[cur * 32 * STA];
#pragma unroll
        for (int kk = 0; kk < 4; kk++) {
            const int k8 = kk * 8;
            uint32_t af[4][4];
            uint32_t bf[4][2];
#pragma unroll
            for (int mt = 0; mt < 4; mt++) {
                const int rt = (wid >> 2) * 4 + mt;
                const uint4 pk = *(const uint4*)&Ac[(kk * 8 + rt) * 128 + lane * 4];
                af[mt][0] = pk.x; af[mt][1] = pk.y; af[mt][2] = pk.z; af[mt][3] = pk.w;
            }
#pragma unroll
            for (int nt = 0; nt < 4; nt++) {
                const int col = wd + nt * 8 + g;
                bf[nt][0] = f2tf(Bc[(k8 + tig) * STA + col]);
                bf[nt][1] = f2tf(Bc[(k8 + tig + 4) * STA + col]);
            }
#pragma unroll
            for (int mt = 0; mt < 4; mt++)
#pragma unroll
                for (int nt = 0; nt < 4; nt++)
                    mma8(acc[mt][nt], af[mt], bf[nt]);
        }
        __syncthreads();
    }

    float* kvp = g_kvp + ((size_t)sp * B_ + b) * C_ * C_;
#pragma unroll
    for (int mt = 0; mt < 4; mt++)
#pragma unroll
        for (int nt = 0; nt < 4; nt++) {
            const int c = c0 + wc + mt * 16 + g;
            const int d = d0 + wd + nt * 8 + tig * 2;
            float2 v0 = make_float2(acc[mt][nt][0], acc[mt][nt][1]);
            float2 v1 = make_float2(acc[mt][nt][2], acc[mt][nt][3]);
            *(float2*)&kvp[(size_t)c * C_ + d]       = v0;
            *(float2*)&kvp[(size_t)(c + 8) * C_ + d] = v1;
        }
}

// ---------------------------------------------------------------------------
// Kernel 2b: reduce SPLITS partials into g_kv in B-fragment-packed tf32 layout.
// Each thread produces one lane's (w0,w1) pair = elements (c,d) and (c+4,d).
// ---------------------------------------------------------------------------
__global__ __launch_bounds__(256) void reduce_kernel() {
    const int idx = blockIdx.x * blockDim.x + threadIdx.x;    // 0 .. 262143
    const int lane = idx & 31;
    const int d8t  = (idx >> 5) & 15;
    const int kk   = (idx >> 9) & 3;
    const int km   = (idx >> 11) & 7;
    const int dt   = (idx >> 14) & 1;
    const int b    = idx >> 15;
    const int g = lane >> 2, tig = lane & 3;
    const int c = km * 32 + kk * 8 + tig;
    const int d = dt * 128 + d8t * 8 + g;

    float s0 = 0.0f, s1 = 0.0f;
#pragma unroll
    for (int sp = 0; sp < SPLITS; sp++) {
        const float* base = g_kvp + ((size_t)(sp * B_ + b) << 16);
        s0 += base[(size_t)c * C_ + d];
        s1 += base[(size_t)(c + 4) * C_ + d];
    }
    uint2 o;
    o.x = f2tf(s0);
    o.y = f2tf(s1);
    *(uint2*)&g_kv[(size_t)idx * 2] = o;
}

// ---------------------------------------------------------------------------
// Kernel 3: out[b][n][d] = sum_c qn[b][n][c] * kv[b][c][d]
// CTA tile 128(n) x 128(d), BK=32, 2-stage pipeline, 2 CTAs/SM.
// Both operands fragment-packed: inner loop = 4 LDS.128 + 4 LDS.64 + 16 MMA.
// ---------------------------------------------------------------------------
__global__ __launch_bounds__(256, 2) void ctx_kernel(float* __restrict__ out) {
    extern __shared__ uint32_t sm[];
    uint32_t* As = sm;              // [2][4096]
    uint32_t* Bs = sm + 2 * 4096;   // [2][4096]

    const int b  = blockIdx.z;
    const int n_tile = blockIdx.y;  // 0..31
    const int dt = blockIdx.x;      // 0..1
    const int n0 = n_tile * 128;
    const int d0 = dt * 128;

    const int t = threadIdx.x, lane = t & 31, wid = t >> 5;
    const int g = lane >> 2, tig = lane & 3;
    const int wn = (wid >> 2) * 64;
    const int wd = (wid & 3) * 32;

    const uint32_t* qb  = g_qn + (size_t)(b * 32 + n_tile) * 32768;
    const uint32_t* kvb = g_kv + (size_t)(b * 2 + dt) * 32768;

    // prologue: stage 0 (km = 0)
    {
#pragma unroll
        for (int i = 0; i < 4; i++) {
            cp16(&As[t * 4 + i * 1024], qb + t * 4 + i * 1024);
            cp16(&Bs[t * 4 + i * 1024], kvb + t * 4 + i * 1024);
        }
        cp_commit();
    }

    float acc[4][4][4] = {};
    const int KM = C_ / 32;   // 8

#pragma unroll 1
    for (int km = 0; km < KM; km++) {
        const int cur = km & 1;
        if (km + 1 < KM) {
            const int nxt = cur ^ 1;
            const uint32_t* sA = qb  + (size_t)(km + 1) * 4096;
            const uint32_t* sB = kvb + (size_t)(km + 1) * 4096;
            uint32_t* An = &As[nxt * 4096];
            uint32_t* Bn = &Bs[nxt * 4096];
#pragma unroll
            for (int i = 0; i < 4; i++) {
                cp16(&An[t * 4 + i * 1024], sA + t * 4 + i * 1024);
                cp16(&Bn[t * 4 + i * 1024], sB + t * 4 + i * 1024);
            }
            cp_commit();
            cp_wait<1>();
        } else {
            cp_wait<0>();
        }
        __syncthreads();

        const uint32_t* Ac = &As[cur * 4096];
        const uint32_t* Bc = &Bs[cur * 4096];
#pragma unroll
        for (int kk = 0; kk < 4; kk++) {
            uint32_t af[4][4];
            uint32_t bf[4][2];
#pragma unroll
            for (int mt = 0; mt < 4; mt++) {
                const int rt = (wid >> 2) * 4 + mt;
                const uint4 pk = *(const uint4*)&Ac[(kk * 8 + rt) * 128 + lane * 4];
                af[mt][0] = pk.x; af[mt][1] = pk.y; af[mt][2] = pk.z; af[mt][3] = pk.w;
            }
#pragma unroll
            for (int nt = 0; nt < 4; nt++) {
                const int d8t = (wid & 3) * 4 + nt;
                const uint2 pk = *(const uint2*)&Bc[(kk * 16 + d8t) * 64 + lane * 2];
                bf[nt][0] = pk.x; bf[nt][1] = pk.y;
            }
#pragma unroll
            for (int mt = 0; mt < 4; mt++)
#pragma unroll
                for (int nt = 0; nt < 4; nt++)
                    mma8(acc[mt][nt], af[mt], bf[nt]);
        }
        __syncthreads();
    }

#pragma unroll
    for (int mt = 0; mt < 4; mt++)
#pragma unroll
        for (int nt = 0; nt < 4; nt++) {
            const int n = n0 + wn + mt * 16 + g;
            const int d = d0 + wd + nt * 8 + tig * 2;
            float2 v0 = make_float2(acc[mt][nt][0], acc[mt][nt][1]);
            float2 v1 = make_float2(acc[mt][nt][2], acc[mt][nt][3]);
            *(float2*)&out[((size_t)b * N_ + n) * C_ + d]       = v0;
            *(float2*)&out[((size_t)b * N_ + n + 8) * C_ + d]   = v1;
        }
}

// ---------------------------------------------------------------------------
extern "C" void kernel_launch(void* const* d_in, const int* in_sizes, int n_in,
                              void* d_out, int out_size) {
    const float* q = (const float*)d_in[0];
    const float* k = (const float*)d_in[1];
    const float* v = (const float*)d_in[2];
    float* out = (float*)d_out;

    const int smem_kv  = (2 * 4096 + 2 * 32 * STA) * 4;   // ~67.6 KB
    const int smem_ctx = (4 * 4096) * 4;                  // 64 KB
    cudaFuncSetAttribute(kv_kernel,  cudaFuncAttributeMaxDynamicSharedMemorySize, smem_kv);
    cudaFuncSetAttribute(ctx_kernel, cudaFuncAttributeMaxDynamicSharedMemorySize, smem_ctx);

    // 1) normalize + tf32 + fragment-pack q and k
    prep_kernel<<<(B_ * N_ + B_ * M_) / 8, 256>>>(q, k);
    // 2) split-K partial kv = kn^T @ v
    kv_kernel<<<dim3(C_ / 128, C_ / 128, B_ * SPLITS), 256, smem_kv>>>(v);
    // 2b) reduce partials -> packed tf32 kv
    reduce_kernel<<<(B_ * C_ * C_ / 2) / 256, 256>>>();
    // 3) out = qn @ kv
    ctx_kernel<<<dim3(C_ / 128, N_ / 128, B_), 256, smem_ctx>>>(out);
}

// round 6
// speedup vs baseline: 1.0736x; 1.0736x over previous
#include <cuda_runtime.h>
#include <cstdint>
#include <cstddef>

#define B_ 8
#define N_ 4096
#define M_ 4096
#define C_ 256

#define SPLITS 8
#define KM_PER_SPLIT 16      // 16 * 32 = 512 m-rows per split
#define STA 136              // stride (words) for kv's raw-v [32][128] tile

#define PSQ 260              // prep q smem stride (words): 260 mod 32 = 4
#define PSK 264              // prep k smem stride (words): 264 mod 32 = 8

// Packed-layout scratch (layouts identical to validated round-4):
// g_qn: [b][n_tile 32][km 8][kk 4][rt 8][lane 32][w 4]   (A-frag for ctx)
// g_kn: [b][c_tile 2][m_chunk 128][kk 4][c16t 8][lane 32][w 4] (A-frag for kv)
// g_kv: [b][d_tile 2][km 8][kk 4][d8t 16][lane 32][w 2]  (B-frag for ctx)
__device__ uint32_t g_qn[B_ * N_ * C_];
__device__ uint32_t g_kn[B_ * M_ * C_];
__device__ float    g_kvp[SPLITS * B_ * C_ * C_];
__device__ uint32_t g_kv[B_ * C_ * C_];

__device__ __forceinline__ uint32_t f2tf(float x) {
    uint32_t r;
    asm("cvt.rna.tf32.f32 %0, %1;" : "=r"(r) : "f"(x));
    return r;
}

__device__ __forceinline__ void mma8(float c[4], const uint32_t a[4], const uint32_t b[2]) {
    asm volatile(
        "mma.sync.aligned.m16n8k8.row.col.f32.tf32.tf32.f32 "
        "{%0,%1,%2,%3}, {%4,%5,%6,%7}, {%8,%9}, {%0,%1,%2,%3};\n"
        : "+f"(c[0]), "+f"(c[1]), "+f"(c[2]), "+f"(c[3])
        : "r"(a[0]), "r"(a[1]), "r"(a[2]), "r"(a[3]),
          "r"(b[0]), "r"(b[1]));
}

__device__ __forceinline__ void cp16(void* smem, const void* gmem) {
    uint32_t s = (uint32_t)__cvta_generic_to_shared(smem);
    asm volatile("cp.async.cg.shared.global [%0], [%1], 16;\n" :: "r"(s), "l"(gmem));
}
__device__ __forceinline__ void cp_commit() { asm volatile("cp.async.commit_group;\n" ::: "memory"); }
template <int NN>
__device__ __forceinline__ void cp_wait() { asm volatile("cp.async.wait_group %0;\n" :: "n"(NN) : "memory"); }

// ---------------------------------------------------------------------------
// Kernel 1a (prep q): CTA = 64 rows of one batch. Coalesced read -> SMEM,
// row norms, then pack into A-fragment blocks with warp-wide 512B stores.
// ---------------------------------------------------------------------------
__global__ __launch_bounds__(256) void prep_q_kernel(const float* __restrict__ q) {
    extern __shared__ float sq[];              // [64][PSQ] + rn[64]
    float* rn = sq + 64 * PSQ;

    const int b    = blockIdx.y;
    const int row0 = blockIdx.x * 64;          // within batch
    const int t = threadIdx.x, lane = t & 31, wid = t >> 5;

    // load + norm: warp handles 8 rows
#pragma unroll
    for (int i = 0; i < 8; i++) {
        const int rl = wid * 8 + i;
        const float* src = q + ((size_t)b * N_ + row0 + rl) * C_;
        float4 a = *(const float4*)(src + lane * 4);
        float4 c = *(const float4*)(src + 128 + lane * 4);
        *(float4*)&sq[rl * PSQ + lane * 4]       = a;
        *(float4*)&sq[rl * PSQ + 128 + lane * 4] = c;
        float ss = a.x * a.x + a.y * a.y + a.z * a.z + a.w * a.w
                 + c.x * c.x + c.y * c.y + c.z * c.z + c.w * c.w;
#pragma unroll
        for (int o = 16; o > 0; o >>= 1) ss += __shfl_xor_sync(0xffffffffu, ss, o);
        if (lane == 0) {
            float r = (ss > 1e-24f) ? rsqrtf(ss) : 1e12f;
            rn[rl] = r * (1.0f / (float)N_);
        }
    }
    __syncthreads();

    // pack: 128 blocks (km 8 x kk 4 x rt_local 4); warp-wide uint4 stores
    const int n_tile = blockIdx.x >> 1;
    const int rt_hi  = (blockIdx.x & 1) * 4;
    const int g = lane >> 2, tig = lane & 3;
    uint32_t* obase = g_qn + (size_t)(b * 32 + n_tile) * 32768;

#pragma unroll 1
    for (int it = 0; it < 16; it++) {
        const int bid = it * 8 + wid;
        const int km = bid >> 4, kk = (bid >> 2) & 3, rt = bid & 3;
        const int c0 = km * 32 + kk * 8 + tig;
        const int r0 = rt * 16 + g;
        const float s0 = rn[r0], s1 = rn[r0 + 8];
        uint4 o;
        o.x = f2tf(sq[r0 * PSQ + c0] * s0);            // h0 j0
        o.y = f2tf(sq[(r0 + 8) * PSQ + c0] * s1);      // h1 j0
        o.z = f2tf(sq[r0 * PSQ + c0 + 4] * s0);        // h0 j1
        o.w = f2tf(sq[(r0 + 8) * PSQ + c0 + 4] * s1);  // h1 j1
        *(uint4*)&obase[(size_t)(((km * 4 + kk) * 8 + rt_hi + rt) * 128) + lane * 4] = o;
    }
}

// ---------------------------------------------------------------------------
// Kernel 1b (prep k): CTA = 64 m-rows. Packs into kv's A-fragment layout.
// ---------------------------------------------------------------------------
__global__ __launch_bounds__(256) void prep_k_kernel(const float* __restrict__ k) {
    extern __shared__ float sk[];              // [64][PSK] + rn[64]
    float* rn = sk + 64 * PSK;

    const int b    = blockIdx.y;
    const int row0 = blockIdx.x * 64;
    const int t = threadIdx.x, lane = t & 31, wid = t >> 5;

#pragma unroll
    for (int i = 0; i < 8; i++) {
        const int rl = wid * 8 + i;
        const float* src = k + ((size_t)b * M_ + row0 + rl) * C_;
        float4 a = *(const float4*)(src + lane * 4);
        float4 c = *(const float4*)(src + 128 + lane * 4);
        *(float4*)&sk[rl * PSK + lane * 4]       = a;
        *(float4*)&sk[rl * PSK + 128 + lane * 4] = c;
        float ss = a.x * a.x + a.y * a.y + a.z * a.z + a.w * a.w
                 + c.x * c.x + c.y * c.y + c.z * c.z + c.w * c.w;
#pragma unroll
        for (int o = 16; o > 0; o >>= 1) ss += __shfl_xor_sync(0xffffffffu, ss, o);
        if (lane == 0) rn[rl] = (ss > 1e-24f) ? rsqrtf(ss) : 1e12f;
    }
    __syncthreads();

    // pack: 128 blocks (ct 2 x mc 2 x kk 4 x c16t 8)
    const int g = lane >> 2, tig = lane & 3;

#pragma unroll 1
    for (int it = 0; it < 16; it++) {
        const int bid = it * 8 + wid;
        const int c16t = bid & 7, kk = (bid >> 3) & 3, mc = (bid >> 5) & 1, ct = bid >> 6;
        const int m_l = mc * 32 + kk * 8 + tig;            // local m row
        const int cc  = ct * 128 + c16t * 16 + g;
        const float s0 = rn[m_l], s1 = rn[m_l + 4];
        uint4 o;
        o.x = f2tf(sk[m_l * PSK + cc] * s0);               // h0 j0
        o.y = f2tf(sk[m_l * PSK + cc + 8] * s0);           // h1 j0
        o.z = f2tf(sk[(m_l + 4) * PSK + cc] * s1);         // h0 j1
        o.w = f2tf(sk[(m_l + 4) * PSK + cc + 8] * s1);     // h1 j1
        const int m_chunk_g = blockIdx.x * 2 + mc;
        size_t off = ((size_t)((b * 2 + ct) * 128 + m_chunk_g)) * 4096
                   + (size_t)(kk * 8 + c16t) * 128 + lane * 4;
        *(uint4*)&g_kn[off] = o;
    }
}

// ---------------------------------------------------------------------------
// Kernel 2: split-K partials of kv (validated round-4 code, unchanged).
// ---------------------------------------------------------------------------
__global__ __launch_bounds__(256, 2) void kv_kernel(const float* __restrict__ v) {
    extern __shared__ uint32_t sm[];
    uint32_t* As = sm;                        // [2][4096]  packed A
    float*    Bs = (float*)(sm + 2 * 4096);   // [2][32*STA] raw fp32

    const int bz = blockIdx.z;
    const int b  = bz >> 3;
    const int sp = bz & 7;
    const int c_tile = blockIdx.y;
    const int c0 = c_tile * 128;
    const int d0 = blockIdx.x * 128;
    const int m_base = sp * (KM_PER_SPLIT * 32);

    const int t = threadIdx.x, lane = t & 31, wid = t >> 5;
    const int g = lane >> 2, tig = lane & 3;
    const int wc = (wid >> 2) * 64;
    const int wd = (wid & 3) * 32;
    const int lr = t >> 3;
    const int lq = (t & 7) * 4;

    const uint32_t* knb = g_kn + (size_t)((b * 2 + c_tile) * 128) * 4096;
    const float*    vb  = v + (size_t)b * M_ * C_ + d0;

    {
        const uint32_t* srcA = knb + (size_t)(sp * KM_PER_SPLIT) * 4096;
#pragma unroll
        for (int i = 0; i < 4; i++)
            cp16(&As[t * 4 + i * 1024], srcA + t * 4 + i * 1024);
#pragma unroll
        for (int i = 0; i < 4; i++)
            cp16(&Bs[lr * STA + lq + i * 32], vb + (size_t)(m_base + lr) * C_ + lq + i * 32);
        cp_commit();
    }

    float acc[4][4][4] = {};

#pragma unroll 1
    for (int km = 0; km < KM_PER_SPLIT; km++) {
        const int cur = km & 1;
        if (km + 1 < KM_PER_SPLIT) {
            const int nxt = cur ^ 1;
            const uint32_t* srcA = knb + (size_t)(sp * KM_PER_SPLIT + km + 1) * 4096;
            uint32_t* An = &As[nxt * 4096];
            float*    Bn = &Bs[nxt * 32 * STA];
            const int m0 = m_base + (km + 1) * 32;
#pragma unroll
            for (int i = 0; i < 4; i++)
                cp16(&An[t * 4 + i * 1024], srcA + t * 4 + i * 1024);
#pragma unroll
            for (int i = 0; i < 4; i++)
                cp16(&Bn[lr * STA + lq + i * 32], vb + (size_t)(m0 + lr) * C_ + lq + i * 32);
            cp_commit();
            cp_wait<1>();
        } else {
            cp_wait<0>();
        }
        __syncthreads();

        const uint32_t* Ac = &As[cur * 4096];
        const float*    Bc = &Bs[cur * 32 * STA];
#pragma unroll
        for (int kk = 0; kk < 4; kk++) {
            const int k8 = kk * 8;
            uint32_t af[4][4];
            uint32_t bf[4][2];
#pragma unroll
            for (int mt = 0; mt < 4; mt++) {
                const int rt = (wid >> 2) * 4 + mt;
                const uint4 pk = *(const uint4*)&Ac[(kk * 8 + rt) * 128 + lane * 4];
                af[mt][0] = pk.x; af[mt][1] = pk.y; af[mt][2] = pk.z; af[mt][3] = pk.w;
            }
#pragma unroll
            for (int nt = 0; nt < 4; nt++) {
                const int col = wd + nt * 8 + g;
                bf[nt][0] = f2tf(Bc[(k8 + tig) * STA + col]);
                bf[nt][1] = f2tf(Bc[(k8 + tig + 4) * STA + col]);
            }
#pragma unroll
            for (int mt = 0; mt < 4; mt++)
#pragma unroll
                for (int nt = 0; nt < 4; nt++)
                    mma8(acc[mt][nt], af[mt], bf[nt]);
        }
        __syncthreads();
    }

    float* kvp = g_kvp + ((size_t)sp * B_ + b) * C_ * C_;
#pragma unroll
    for (int mt = 0; mt < 4; mt++)
#pragma unroll
        for (int nt = 0; nt < 4; nt++) {
            const int c = c0 + wc + mt * 16 + g;
            const int d = d0 + wd + nt * 8 + tig * 2;
            float2 v0 = make_float2(acc[mt][nt][0], acc[mt][nt][1]);
            float2 v1 = make_float2(acc[mt][nt][2], acc[mt][nt][3]);
            *(float2*)&kvp[(size_t)c * C_ + d]       = v0;
            *(float2*)&kvp[(size_t)(c + 8) * C_ + d] = v1;
        }
}

// ---------------------------------------------------------------------------
// Kernel 2b: reduce partials -> packed tf32 B-frags (round-4, unchanged).
// ---------------------------------------------------------------------------
__global__ __launch_bounds__(256) void reduce_kernel() {
    const int idx = blockIdx.x * blockDim.x + threadIdx.x;
    const int lane = idx & 31;
    const int d8t  = (idx >> 5) & 15;
    const int kk   = (idx >> 9) & 3;
    const int km   = (idx >> 11) & 7;
    const int dt   = (idx >> 14) & 1;
    const int b    = idx >> 15;
    const int g = lane >> 2, tig = lane & 3;
    const int c = km * 32 + kk * 8 + tig;
    const int d = dt * 128 + d8t * 8 + g;

    float s0 = 0.0f, s1 = 0.0f;
#pragma unroll
    for (int sp = 0; sp < SPLITS; sp++) {
        const float* base = g_kvp + ((size_t)(sp * B_ + b) << 16);
        s0 += base[(size_t)c * C_ + d];
        s1 += base[(size_t)(c + 4) * C_ + d];
    }
    uint2 o;
    o.x = f2tf(s0);
    o.y = f2tf(s1);
    *(uint2*)&g_kv[(size_t)idx * 2] = o;
}

// ---------------------------------------------------------------------------
// Kernel 3: ctx GEMM (validated round-4 code, unchanged).
// ---------------------------------------------------------------------------
__global__ __launch_bounds__(256, 2) void ctx_kernel(float* __restrict__ out) {
    extern __shared__ uint32_t sm[];
    uint32_t* As = sm;              // [2][4096]
    uint32_t* Bs = sm + 2 * 4096;   // [2][4096]

    const int b  = blockIdx.z;
    const int n_tile = blockIdx.y;
    const int dt = blockIdx.x;
    const int n0 = n_tile * 128;
    const int d0 = dt * 128;

    const int t = threadIdx.x, lane = t & 31, wid = t >> 5;
    const int g = lane >> 2, tig = lane & 3;
    const int wn = (wid >> 2) * 64;
    const int wd = (wid & 3) * 32;

    const uint32_t* qb  = g_qn + (size_t)(b * 32 + n_tile) * 32768;
    const uint32_t* kvb = g_kv + (size_t)(b * 2 + dt) * 32768;

    {
#pragma unroll
        for (int i = 0; i < 4; i++) {
            cp16(&As[t * 4 + i * 1024], qb + t * 4 + i * 1024);
            cp16(&Bs[t * 4 + i * 1024], kvb + t * 4 + i * 1024);
        }
        cp_commit();
    }

    float acc[4][4][4] = {};
    const int KM = C_ / 32;   // 8

#pragma unroll 1
    for (int km = 0; km < KM; km++) {
        const int cur = km & 1;
        if (km + 1 < KM) {
            const int nxt = cur ^ 1;
            const uint32_t* sA = qb  + (size_t)(km + 1) * 4096;
            const uint32_t* sB = kvb + (size_t)(km + 1) * 4096;
            uint32_t* An = &As[nxt * 4096];
            uint32_t* Bn = &Bs[nxt * 4096];
#pragma unroll
            for (int i = 0; i < 4; i++) {
                cp16(&An[t * 4 + i * 1024], sA + t * 4 + i * 1024);
                cp16(&Bn[t * 4 + i * 1024], sB + t * 4 + i * 1024);
            }
            cp_commit();
            cp_wait<1>();
        } else {
            cp_wait<0>();
        }
        __syncthreads();

        const uint32_t* Ac = &As[cur * 4096];
        const uint32_t* Bc = &Bs[cur * 4096];
#pragma unroll
        for (int kk = 0; kk < 4; kk++) {
            uint32_t af[4][4];
            uint32_t bf[4][2];
#pragma unroll
            for (int mt = 0; mt < 4; mt++) {
                const int rt = (wid >> 2) * 4 + mt;
                const uint4 pk = *(const uint4*)&Ac[(kk * 8 + rt) * 128 + lane * 4];
                af[mt][0] = pk.x; af[mt][1] = pk.y; af[mt][2] = pk.z; af[mt][3] = pk.w;
            }
#pragma unroll
            for (int nt = 0; nt < 4; nt++) {
                const int d8t = (wid & 3) * 4 + nt;
                const uint2 pk = *(const uint2*)&Bc[(kk * 16 + d8t) * 64 + lane * 2];
                bf[nt][0] = pk.x; bf[nt][1] = pk.y;
            }
#pragma unroll
            for (int mt = 0; mt < 4; mt++)
#pragma unroll
                for (int nt = 0; nt < 4; nt++)
                    mma8(acc[mt][nt], af[mt], bf[nt]);
        }
        __syncthreads();
    }

#pragma unroll
    for (int mt = 0; mt < 4; mt++)
#pragma unroll
        for (int nt = 0; nt < 4; nt++) {
            const int n = n0 + wn + mt * 16 + g;
            const int d = d0 + wd + nt * 8 + tig * 2;
            float2 v0 = make_float2(acc[mt][nt][0], acc[mt][nt][1]);
            float2 v1 = make_float2(acc[mt][nt][2], acc[mt][nt][3]);
            *(float2*)&out[((size_t)b * N_ + n) * C_ + d]       = v0;
            *(float2*)&out[((size_t)b * N_ + n + 8) * C_ + d]   = v1;
        }
}

// ---------------------------------------------------------------------------
extern "C" void kernel_launch(void* const* d_in, const int* in_sizes, int n_in,
                              void* d_out, int out_size) {
    const float* q = (const float*)d_in[0];
    const float* k = (const float*)d_in[1];
    const float* v = (const float*)d_in[2];
    float* out = (float*)d_out;

    const int smem_pq  = (64 * PSQ + 64) * 4;             // ~66.8 KB
    const int smem_pk  = (64 * PSK + 64) * 4;             // ~67.8 KB
    const int smem_kv  = (2 * 4096 + 2 * 32 * STA) * 4;   // ~67.6 KB
    const int smem_ctx = (4 * 4096) * 4;                  // 64 KB
    cudaFuncSetAttribute(prep_q_kernel, cudaFuncAttributeMaxDynamicSharedMemorySize, smem_pq);
    cudaFuncSetAttribute(prep_k_kernel, cudaFuncAttributeMaxDynamicSharedMemorySize, smem_pk);
    cudaFuncSetAttribute(kv_kernel,  cudaFuncAttributeMaxDynamicSharedMemorySize, smem_kv);
    cudaFuncSetAttribute(ctx_kernel, cudaFuncAttributeMaxDynamicSharedMemorySize, smem_ctx);

    // 1) normalize + tf32 + fragment-pack (coalesced via SMEM staging)
    prep_k_kernel<<<dim3(M_ / 64, B_), 256, smem_pk>>>(k);
    prep_q_kernel<<<dim3(N_ / 64, B_), 256, smem_pq>>>(q);
    // 2) split-K partial kv = kn^T @ v
    kv_kernel<<<dim3(C_ / 128, C_ / 128, B_ * SPLITS), 256, smem_kv>>>(v);
    // 2b) reduce partials -> packed tf32 kv
    reduce_kernel<<<(B_ * C_ * C_ / 2) / 256, 256>>>();
    // 3) out = qn @ kv
    ctx_kernel<<<dim3(C_ / 128, N_ / 128, B_), 256, smem_ctx>>>(out);
}